// round 16
// baseline (speedup 1.0000x reference)
#include <cuda_runtime.h>
#include <cuda_fp16.h>

// ---------------- problem constants ----------------
constexpr int Bn = 4;
constexpr int Sn = 4096;
constexpr int Hn = 16;
constexpr int BHn = 64;
constexpr int NSPLIT = 16;
constexpr int SCHUNK = Sn / NSPLIT;   // 256
constexpr int CH  = 64;               // s-rows per staged chunk
constexpr int NCH = SCHUNK / CH;      // 4
constexpr float PIC = 3.1415f;        // verbatim constant from reference

// ---------------- static device scratch ----------------
__device__ float    g_part  [NSPLIT * 64 * 8192];  // slot x bh x [64x128] fp32 (KV | KVp)
__device__ float    g_partKs[NSPLIT * 64 * 128];   // slot x bh x [ksum|kpsum]
__device__ unsigned g_Mst   [64 * 4096];           // bh x {M halves [64x64] ; Mp halves}
__device__ float    g_Ks    [64 * 128];            // bh x stacked [Ksum;Kpsum] fp32
__device__ unsigned g_Wqh   [16 * 2048];           // h x Wq halves [d=64][n=64]

// ---------------- helpers ----------------
__device__ __forceinline__ void mma16h(float* c,
    unsigned a0, unsigned a1, unsigned a2, unsigned a3, unsigned b0, unsigned b1)
{
    asm volatile(
        "mma.sync.aligned.m16n8k16.row.col.f32.f16.f16.f32 "
        "{%0,%1,%2,%3},{%4,%5,%6,%7},{%8,%9},{%0,%1,%2,%3};"
        : "+f"(c[0]), "+f"(c[1]), "+f"(c[2]), "+f"(c[3])
        : "r"(a0), "r"(a1), "r"(a2), "r"(a3), "r"(b0), "r"(b1));
}
__device__ __forceinline__ void ldsm4t(unsigned& r0, unsigned& r1, unsigned& r2, unsigned& r3,
                                       unsigned addr)
{
    asm volatile("ldmatrix.sync.aligned.m8n8.x4.trans.shared.b16 {%0,%1,%2,%3}, [%4];"
        : "=r"(r0), "=r"(r1), "=r"(r2), "=r"(r3) : "r"(addr));
}
__device__ __forceinline__ unsigned h2u(float a, float b) {
    __half2 h = __floats2half2_rn(a, b);
    return *reinterpret_cast<unsigned*>(&h);
}
__device__ __forceinline__ void cpa16(unsigned dst, const void* src) {
    asm volatile("cp.async.cg.shared.global [%0], [%1], 16;" :: "r"(dst), "l"(src));
}
__device__ __forceinline__ void cpa_commit() { asm volatile("cp.async.commit_group;"); }
__device__ __forceinline__ void cpa_wait0()  { asm volatile("cp.async.wait_group 0;"); }
__device__ __forceinline__ float elu1(float v) { return v > 0.f ? v + 1.f : __expf(v); }

// ===========================================================================
// Kernel 0: convert Wq head slices to packed halves g_Wqh[h][d][n].
// ===========================================================================
__global__ __launch_bounds__(256)
void wqprep_kernel(const float2* __restrict__ wq_w2)
{
    const int h = blockIdx.x, tid = threadIdx.x;
    #pragma unroll
    for (int t = 0; t < 8; t++) {
        int w = tid + t * 256;            // word over 2048
        int d = w >> 5, cp = w & 31;
        float2 v = wq_w2[d * 512 + h * 32 + cp];
        g_Wqh[h * 2048 + w] = h2u(v.x, v.y);
    }
}

// ===========================================================================
// Kernel 1 (tensor, fp16 operands) — R14/R15-proven version (clock probe):
// ===========================================================================
__global__ __launch_bounds__(256, 2)
void kv_kernel(const float4* __restrict__ key4, const float4* __restrict__ value4,
               const float4* __restrict__ wk_w4, const float* __restrict__ wk_b)
{
    extern __shared__ unsigned smu[];
    unsigned* hWkw = smu;                 // Wk  [k=d][n] halves, stride 72h (36w): 2304w
    unsigned* hKw  = hWkw + 2304;         // rawK [s][d] halves, stride 72h: 2304w
    unsigned* hVw  = hKw  + 2304;         // [V|sinV] [s][z] halves, stride 136h (68w): 4352w
    unsigned* hAw  = hVw  + 4352;         // kp^T [x][s] halves, stride 72h: 2304w
    float* sSin  = (float*)(hAw + 2304);  // 64
    float* sBias = sSin + 64;             // 64
    float* sKred = sBias + 64;            // 4 x 128
    __half* hAh = (__half*)hAw;

    const int bh = blockIdx.x, split = blockIdx.y;
    const int b  = bh >> 4,   h     = bh & 15;
    const int tid = threadIdx.x;
    const int lane = tid & 31, wid = tid >> 5;
    const int g = lane >> 2, tig = lane & 3;
    const int sbase = split * SCHUNK;
    const int rowp = ((lane >> 3) & 1) * 8 + (lane & 7);
    const int colp = (lane >> 4) * 8;

    const unsigned wkBase = (unsigned)__cvta_generic_to_shared(hWkw);
    const unsigned vBase  = (unsigned)__cvta_generic_to_shared(hVw);

    #pragma unroll
    for (int t = 0; t < 4; t++) {
        int idx = tid + t * 256; int d = idx >> 4, c4 = idx & 15;
        float4 w = wk_w4[d * 256 + h * 16 + c4];
        *(uint2*)&hWkw[d * 36 + 2 * c4] = make_uint2(h2u(w.x, w.y), h2u(w.z, w.w));
    }
    if (tid < 64) sBias[tid] = wk_b[h * 64 + tid];

    #pragma unroll
    for (int t = 0; t < 4; t++) {
        int idx = tid + t * 256; int r = idx >> 4, c4 = idx & 15;
        size_t gi = ((size_t)(b * Sn + sbase + r)) * 16 + c4;
        float4 k = key4[gi], v = value4[gi];
        *(uint2*)&hKw[r * 36 + 2 * c4] = make_uint2(h2u(k.x, k.y), h2u(k.z, k.w));
        float sn = __sinf(PIC * (float)(sbase + r) / (float)Sn);
        *(uint2*)&hVw[r * 68 + 2 * c4]      = make_uint2(h2u(v.x, v.y), h2u(v.z, v.w));
        *(uint2*)&hVw[r * 68 + 32 + 2 * c4] = make_uint2(h2u(v.x*sn, v.y*sn), h2u(v.z*sn, v.w*sn));
    }
    if (tid < 64) sSin[tid] = __sinf(PIC * (float)(sbase + tid) / (float)Sn);
    __syncthreads();

    const int m0p = (wid & 3) * 16;
    const int n0p = (wid >> 2) * 32;
    const int x0 = (wid & 1) * 32;
    const int z0 = (wid >> 1) * 32;

    float acc[2][4][4];
    #pragma unroll
    for (int i = 0; i < 2; i++)
        #pragma unroll
        for (int nt = 0; nt < 4; nt++)
            #pragma unroll
            for (int j = 0; j < 4; j++) acc[i][nt][j] = 0.f;
    float kc[4][2], kpc[4][2];
    #pragma unroll
    for (int nt = 0; nt < 4; nt++) { kc[nt][0]=kc[nt][1]=kpc[nt][0]=kpc[nt][1]=0.f; }

    for (int cc = 0; cc < NCH; cc++) {
        float pc[4][4];
        #pragma unroll
        for (int nt = 0; nt < 4; nt++) {
            int col0 = n0p + 8 * nt + 2 * tig;
            pc[nt][0] = sBias[col0]; pc[nt][1] = sBias[col0 + 1];
            pc[nt][2] = sBias[col0]; pc[nt][3] = sBias[col0 + 1];
        }
        #pragma unroll
        for (int ks = 0; ks < 4; ks++) {
            int kw = ks * 8;
            unsigned a0 = hKw[(m0p + g)     * 36 + kw + tig];
            unsigned a1 = hKw[(m0p + g + 8) * 36 + kw + tig];
            unsigned a2 = hKw[(m0p + g)     * 36 + kw + tig + 4];
            unsigned a3 = hKw[(m0p + g + 8) * 36 + kw + tig + 4];
            #pragma unroll
            for (int p = 0; p < 2; p++) {
                unsigned b0, b1, b2, b3;
                unsigned ad = wkBase + ((16 * ks + rowp) * 72 + n0p + 16 * p + colp) * 2;
                ldsm4t(b0, b1, b2, b3, ad);
                mma16h(pc[2 * p],     a0, a1, a2, a3, b0, b1);
                mma16h(pc[2 * p + 1], a0, a1, a2, a3, b2, b3);
            }
        }

        {
            int s1 = m0p + g, s2 = m0p + g + 8;
            float sn1 = sSin[s1], sn2 = sSin[s2];
            #pragma unroll
            for (int nt = 0; nt < 4; nt++) {
                int col0 = n0p + 8 * nt + 2 * tig;
                float v00 = elu1(pc[nt][0]), v01 = elu1(pc[nt][1]);
                float v10 = elu1(pc[nt][2]), v11 = elu1(pc[nt][3]);
                kc [nt][0] += v00 + v10;           kc [nt][1] += v01 + v11;
                kpc[nt][0] += v00*sn1 + v10*sn2;   kpc[nt][1] += v01*sn1 + v11*sn2;
                hAh[(col0)     * 72 + s1] = __float2half_rn(v00);
                hAh[(col0 + 1) * 72 + s1] = __float2half_rn(v01);
                hAh[(col0)     * 72 + s2] = __float2half_rn(v10);
                hAh[(col0 + 1) * 72 + s2] = __float2half_rn(v11);
            }
        }
        __syncthreads();

        #pragma unroll
        for (int ks = 0; ks < 4; ks++) {
            int kw = ks * 8;
            unsigned a[2][4];
            #pragma unroll
            for (int i = 0; i < 2; i++) {
                int xr = x0 + 16 * i + g;
                a[i][0] = hAw[xr       * 36 + kw + tig];
                a[i][1] = hAw[(xr + 8) * 36 + kw + tig];
                a[i][2] = hAw[xr       * 36 + kw + tig + 4];
                a[i][3] = hAw[(xr + 8) * 36 + kw + tig + 4];
            }
            #pragma unroll
            for (int p = 0; p < 2; p++) {
                unsigned b0, b1, b2, b3;
                unsigned ad = vBase + ((16 * ks + rowp) * 136 + z0 + 16 * p + colp) * 2;
                ldsm4t(b0, b1, b2, b3, ad);
                #pragma unroll
                for (int i = 0; i < 2; i++) {
                    mma16h(acc[i][2 * p],     a[i][0], a[i][1], a[i][2], a[i][3], b0, b1);
                    mma16h(acc[i][2 * p + 1], a[i][0], a[i][1], a[i][2], a[i][3], b2, b3);
                }
            }
        }
        __syncthreads();

        if (cc + 1 < NCH) {
            int scs = sbase + (cc + 1) * CH;
            #pragma unroll
            for (int t = 0; t < 4; t++) {
                int idx = tid + t * 256; int r = idx >> 4, c4 = idx & 15;
                size_t gi = ((size_t)(b * Sn + scs + r)) * 16 + c4;
                float4 k = key4[gi], v = value4[gi];
                *(uint2*)&hKw[r * 36 + 2 * c4] = make_uint2(h2u(k.x, k.y), h2u(k.z, k.w));
                float sn = __sinf(PIC * (float)(scs + r) / (float)Sn);
                *(uint2*)&hVw[r * 68 + 2 * c4]      = make_uint2(h2u(v.x, v.y), h2u(v.z, v.w));
                *(uint2*)&hVw[r * 68 + 32 + 2 * c4] = make_uint2(h2u(v.x*sn, v.y*sn), h2u(v.z*sn, v.w*sn));
            }
            if (tid < 64) sSin[tid] = __sinf(PIC * (float)(scs + tid) / (float)Sn);
            __syncthreads();
        }
    }

    {
        size_t base = ((size_t)(split * 64 + bh)) * 8192;
        #pragma unroll
        for (int i = 0; i < 2; i++)
            #pragma unroll
            for (int nt = 0; nt < 4; nt++) {
                int x = x0 + 16 * i + g;
                int z = z0 + 8 * nt + 2 * tig;
                *(float2*)&g_part[base + (size_t)x       * 128 + z] = make_float2(acc[i][nt][0], acc[i][nt][1]);
                *(float2*)&g_part[base + (size_t)(x + 8) * 128 + z] = make_float2(acc[i][nt][2], acc[i][nt][3]);
            }
    }

    #pragma unroll
    for (int off = 4; off <= 16; off <<= 1)
        #pragma unroll
        for (int nt = 0; nt < 4; nt++)
            #pragma unroll
            for (int e = 0; e < 2; e++) {
                kc [nt][e] += __shfl_xor_sync(0xffffffffu, kc [nt][e], off);
                kpc[nt][e] += __shfl_xor_sync(0xffffffffu, kpc[nt][e], off);
            }
    if (g == 0) {
        int mt = wid & 3;
        #pragma unroll
        for (int nt = 0; nt < 4; nt++)
            #pragma unroll
            for (int e = 0; e < 2; e++) {
                int x = n0p + 8 * nt + 2 * tig + e;
                sKred[mt * 128 + x]      = kc [nt][e];
                sKred[mt * 128 + 64 + x] = kpc[nt][e];
            }
    }
    __syncthreads();
    if (tid < 128)
        g_partKs[(split * 64 + bh) * 128 + tid] =
            sKred[tid] + sKred[128 + tid] + sKred[256 + tid] + sKred[384 + tid];
}

// ===========================================================================
// Kernel 2: per bh — reduce partials, fold V-proj + dense (R15):
//   M/Mp -> g_Mst as PACKED HALF matrices [bh][{M,Mp}][k=64][n=64].
// ===========================================================================
constexpr int PAD = 68;
__global__ __launch_bounds__(256)
void mprep_kernel(const float* __restrict__ wv_w, const float* __restrict__ wv_b,
                  const float* __restrict__ dense_w)
{
    extern __shared__ float sm[];
    float* sC    = sm;                   // 128*68
    float* sWv   = sC   + 128 * PAD;
    float* sWd   = sWv  + 64 * PAD;
    float* sG    = sWd  + 64 * PAD;
    float* sKsum = sG   + 64 * PAD;      // 128
    float* sBvd  = sKsum + 128;          // 64
    const float4* g_part4 = (const float4*)g_part;

    const int bh = blockIdx.x, h = bh & 15, tid = threadIdx.x;

    #pragma unroll
    for (int t = 0; t < 16; t++) {
        int i = tid + t * 256; int k = i >> 6, c = i & 63;
        sWv[k * PAD + c] = wv_w[k * 1024 + h * 64 + c];
        sWd[k * PAD + c] = dense_w[(h * 64 + k) * 64 + c];
    }
    #pragma unroll
    for (int t = 0; t < 8; t++) {
        int idx = tid + t * 256;
        int x = idx >> 5, c8 = idx & 31;
        float4 s = make_float4(0.f, 0.f, 0.f, 0.f);
        for (int sl = 0; sl < NSPLIT; sl++) {
            float4 v = g_part4[((size_t)(sl * 64 + bh)) * 2048 + idx];
            s.x += v.x; s.y += v.y; s.z += v.z; s.w += v.w;
        }
        int row = (c8 < 16) ? x : (x + 64);
        int c4  = c8 & 15;
        *(float4*)&sC[row * PAD + c4 * 4] = s;
    }
    if (tid < 128) {
        float s = 0.f;
        for (int sl = 0; sl < NSPLIT; sl++) s += g_partKs[(sl * 64 + bh) * 128 + tid];
        sKsum[tid] = s;
        g_Ks[bh * 128 + tid] = s;
    }
    __syncthreads();

    const int r  = tid >> 2;
    const int c0 = (tid & 3) * 16;

    {
        float a16[16];
        #pragma unroll
        for (int j = 0; j < 16; j++) a16[j] = 0.f;
        for (int kk = 0; kk < 64; kk++) {
            float a = sWv[r * PAD + kk];
            #pragma unroll
            for (int j = 0; j < 16; j++) a16[j] += a * sWd[kk * PAD + c0 + j];
        }
        #pragma unroll
        for (int j = 0; j < 16; j++) sG[r * PAD + c0 + j] = a16[j];
    }
    if (tid < 64) {
        float s = 0.f;
        for (int c = 0; c < 64; c++) s += wv_b[h * 64 + c] * sWd[c * PAD + tid];
        sBvd[tid] = s;
    }
    __syncthreads();

    {
        float m0[16], m1[16];
        #pragma unroll
        for (int j = 0; j < 16; j++) { m0[j] = 0.f; m1[j] = 0.f; }
        for (int kk = 0; kk < 64; kk++) {
            float a0 = sC[r * PAD + kk];
            float a1 = sC[(r + 64) * PAD + kk];
            #pragma unroll
            for (int j = 0; j < 16; j++) {
                float gv = sG[kk * PAD + c0 + j];
                m0[j] += a0 * gv; m1[j] += a1 * gv;
            }
        }
        float k0 = sKsum[r], k1 = sKsum[r + 64];
        #pragma unroll
        for (int j = 0; j < 16; j++) {
            m0[j] += k0 * sBvd[c0 + j];
            m1[j] += k1 * sBvd[c0 + j];
        }
        unsigned* dstW = &g_Mst[(size_t)bh * 4096];
        #pragma unroll
        for (int j = 0; j < 16; j += 2) {
            dstW[r * 32 + (c0 + j) / 2]        = h2u(m0[j], m0[j + 1]);
            dstW[2048 + r * 32 + (c0 + j) / 2] = h2u(m1[j], m1[j + 1]);
        }
    }
}

// ===========================================================================
// Kernel 3 (tensor, fp16, cp.async double-buffered staging):
//   per (b, 64-row s-tile), loop heads; all per-head operands (Wq halves,
//   M/Mp halves, Ks, bq) arrive via cp.async overlapped with prior head.
// ===========================================================================
constexpr int W_QRAW = 0;
constexpr int W_Q    = 2304;
constexpr int W_BUF  = 4608;
constexpr int BUFW   = 7104;   // hWq 2304 | hM 2304 | hMp 2304 | Ks 128 | Qb 64
constexpr int W_WS   = W_BUF + 2 * BUFW;   // 18816
constexpr int W_DOT  = W_WS + 64;          // 18880
constexpr int W_END  = W_DOT + 256;        // 19136 words = 76544 B

__global__ __launch_bounds__(256, 2)
void out_kernel(const float4* __restrict__ query4,
                const float*  __restrict__ wq_b,
                const float*  __restrict__ dense_b, float* __restrict__ out)
{
    extern __shared__ unsigned smu[];
    unsigned* hQraw = smu + W_QRAW;
    unsigned* hQ    = smu + W_Q;
    float* sWs  = (float*)(smu + W_WS);
    float* sDot = (float*)(smu + W_DOT);
    __half* hQh = (__half*)hQ;

    const int b  = blockIdx.y;
    const int s0 = blockIdx.x * 64;
    const int tid = threadIdx.x;
    const int lane = tid & 31, wid = tid >> 5;
    const int g = lane >> 2, tig = lane & 3;
    const int mt = wid & 3, nh = wid >> 2;
    const int m0 = mt * 16, n0 = nh * 32;
    const int rowp = ((lane >> 3) & 1) * 8 + (lane & 7);
    const int colp = (lane >> 4) * 8;

    const unsigned smemBase = (unsigned)__cvta_generic_to_shared(smu);

    // issue cp.async staging for head hh into buffer `buf`
    auto stage = [&](int buf, int hh) {
        unsigned base = smemBase + (W_BUF + buf * BUFW) * 4;
        #pragma unroll
        for (int t = 0; t < 2; t++) {                       // Wq: 512 x 16B
            int idx = tid + t * 256; int d = idx >> 3, cc = idx & 7;
            cpa16(base + d * 144 + cc * 16,
                  (const char*)g_Wqh + (size_t)hh * 8192 + d * 128 + cc * 16);
        }
        #pragma unroll
        for (int t = 0; t < 4; t++) {                       // M/Mp: 1024 x 16B
            int idx = tid + t * 256; int mat = idx >> 9, r = (idx >> 3) & 63, cc = idx & 7;
            cpa16(base + (2304 + mat * 2304) * 4 + r * 144 + cc * 16,
                  (const char*)g_Mst + (size_t)(b * 16 + hh) * 16384 + mat * 8192 + r * 128 + cc * 16);
        }
        if (tid < 32)                                       // Ks: 512B
            cpa16(base + 6912 * 4 + tid * 16,
                  (const char*)g_Ks + (size_t)(b * 16 + hh) * 512 + tid * 16);
        else if (tid < 48)                                  // Qb: 256B
            cpa16(base + 7040 * 4 + (tid - 32) * 16,
                  (const char*)wq_b + (size_t)hh * 256 + (tid - 32) * 16);
        cpa_commit();
    };

    // prologue: start head 0 copies, then stage raw Q halves + pos weights
    stage(0, 0);
    #pragma unroll
    for (int t = 0; t < 4; t++) {
        int idx = tid + t * 256; int r = idx >> 4, c4 = idx & 15;
        float4 q = query4[((size_t)(b * Sn + s0 + r)) * 16 + c4];
        *(uint2*)&hQraw[r * 36 + 2 * c4] = make_uint2(h2u(q.x, q.y), h2u(q.z, q.w));
    }
    if (tid < 64) {
        float ps = PIC * (float)(s0 + tid) / (float)Sn;
        sWs[tid] = __cosf(ps) + __sinf(ps);
    }

    float accO[4][4];
    #pragma unroll
    for (int nt = 0; nt < 4; nt++)
        #pragma unroll
        for (int j = 0; j < 4; j++) accO[nt][j] = 0.f;

    int cur = 0;
    for (int h = 0; h < Hn; h++) {
        cpa_wait0();
        __syncthreads();                 // buf[cur] ready for all; prev readers done
        if (h + 1 < Hn) stage(cur ^ 1, h + 1);

        unsigned* hWq = smu + W_BUF + cur * BUFW;
        unsigned* hM  = hWq + 2304;
        unsigned* hMp = hWq + 4608;
        float* sKs = (float*)(hWq + 6912);
        float* sQb = (float*)(hWq + 7040);
        const unsigned wqBase = smemBase + (W_BUF + cur * BUFW) * 4;
        const unsigned mBase  = wqBase + 2304 * 4;
        const unsigned mpBase = wqBase + 4608 * 4;

        // ---- q projection mma (f16 k16) ----
        float pc[4][4];
        #pragma unroll
        for (int nt = 0; nt < 4; nt++) {
            int col0 = n0 + 8 * nt + 2 * tig;
            pc[nt][0] = sQb[col0]; pc[nt][1] = sQb[col0 + 1];
            pc[nt][2] = sQb[col0]; pc[nt][3] = sQb[col0 + 1];
        }
        #pragma unroll
        for (int ks = 0; ks < 4; ks++) {
            int kw = ks * 8;
            unsigned a0 = hQraw[(m0 + g)     * 36 + kw + tig];
            unsigned a1 = hQraw[(m0 + g + 8) * 36 + kw + tig];
            unsigned a2 = hQraw[(m0 + g)     * 36 + kw + tig + 4];
            unsigned a3 = hQraw[(m0 + g + 8) * 36 + kw + tig + 4];
            #pragma unroll
            for (int p = 0; p < 2; p++) {
                unsigned b0, b1, b2, b3;
                unsigned ad = wqBase + ((16 * ks + rowp) * 72 + n0 + 16 * p + colp) * 2;
                ldsm4t(b0, b1, b2, b3, ad);
                mma16h(pc[2 * p],     a0, a1, a2, a3, b0, b1);
                mma16h(pc[2 * p + 1], a0, a1, a2, a3, b2, b3);
            }
        }

        // ---- elu, partial denominators, half-store q [s][x] ----
        {
            int r1 = (m0 + g) * 72, r2 = (m0 + g + 8) * 72;
            float d0a = 0.f, d1a = 0.f, d0b = 0.f, d1b = 0.f;
            #pragma unroll
            for (int nt = 0; nt < 4; nt++) {
                int col0 = n0 + 8 * nt + 2 * tig;
                float ks0 = sKs[col0],      ks1 = sKs[col0 + 1];
                float kp0 = sKs[64 + col0], kp1 = sKs[64 + col0 + 1];
                float v00 = elu1(pc[nt][0]), v01 = elu1(pc[nt][1]);
                float v10 = elu1(pc[nt][2]), v11 = elu1(pc[nt][3]);
                d0a += v00 * ks0 + v01 * ks1;  d1a += v00 * kp0 + v01 * kp1;
                d0b += v10 * ks0 + v11 * ks1;  d1b += v10 * kp0 + v11 * kp1;
                hQh[r1 + col0]     = __float2half_rn(v00);
                hQh[r1 + col0 + 1] = __float2half_rn(v01);
                hQh[r2 + col0]     = __float2half_rn(v10);
                hQh[r2 + col0 + 1] = __float2half_rn(v11);
            }
            d0a += __shfl_xor_sync(0xffffffffu, d0a, 1); d0a += __shfl_xor_sync(0xffffffffu, d0a, 2);
            d1a += __shfl_xor_sync(0xffffffffu, d1a, 1); d1a += __shfl_xor_sync(0xffffffffu, d1a, 2);
            d0b += __shfl_xor_sync(0xffffffffu, d0b, 1); d0b += __shfl_xor_sync(0xffffffffu, d0b, 2);
            d1b += __shfl_xor_sync(0xffffffffu, d1b, 1); d1b += __shfl_xor_sync(0xffffffffu, d1b, 2);
            if (tig == 0) {
                sDot[(m0 + g) * 4 + nh]         = d0a;
                sDot[(m0 + g) * 4 + 2 + nh]     = d1a;
                sDot[(m0 + g + 8) * 4 + nh]     = d0b;
                sDot[(m0 + g + 8) * 4 + 2 + nh] = d1b;
            }
        }
        __syncthreads();

        int r1 = m0 + g, r2 = m0 + g + 8;
        float w1 = sWs[r1], w2 = sWs[r2];
        float den1 = 1.0f / (sDot[r1 * 4] + sDot[r1 * 4 + 1]
                     + w1 * (sDot[r1 * 4 + 2] + sDot[r1 * 4 + 3]) + 1e-5f);
        float den2 = 1.0f / (sDot[r2 * 4] + sDot[r2 * 4 + 1]
                     + w2 * (sDot[r2 * 4 + 2] + sDot[r2 * 4 + 3]) + 1e-5f);
        float dnw1 = den1 * w1, dnw2 = den2 * w2;

        // ---- split o-GEMM (f16 k16) ----
        float ocM[4][4], ocP[4][4];
        #pragma unroll
        for (int nt = 0; nt < 4; nt++)
            #pragma unroll
            for (int j = 0; j < 4; j++) { ocM[nt][j] = 0.f; ocP[nt][j] = 0.f; }
        #pragma unroll
        for (int ks = 0; ks < 4; ks++) {
            int kw = ks * 8;
            unsigned a0 = hQ[(m0 + g)     * 36 + kw + tig];
            unsigned a1 = hQ[(m0 + g + 8) * 36 + kw + tig];
            unsigned a2 = hQ[(m0 + g)     * 36 + kw + tig + 4];
            unsigned a3 = hQ[(m0 + g + 8) * 36 + kw + tig + 4];
            #pragma unroll
            for (int p = 0; p < 2; p++) {
                unsigned rowoff = ((16 * ks + rowp) * 72 + n0 + 16 * p + colp) * 2;
                unsigned b0, b1, b2, b3;
                ldsm4t(b0, b1, b2, b3, mBase + rowoff);
                mma16h(ocM[2 * p],     a0, a1, a2, a3, b0, b1);
                mma16h(ocM[2 * p + 1], a0, a1, a2, a3, b2, b3);
                ldsm4t(b0, b1, b2, b3, mpBase + rowoff);
                mma16h(ocP[2 * p],     a0, a1, a2, a3, b0, b1);
                mma16h(ocP[2 * p + 1], a0, a1, a2, a3, b2, b3);
            }
        }
        #pragma unroll
        for (int nt = 0; nt < 4; nt++) {
            accO[nt][0] += den1 * ocM[nt][0] + dnw1 * ocP[nt][0];
            accO[nt][1] += den1 * ocM[nt][1] + dnw1 * ocP[nt][1];
            accO[nt][2] += den2 * ocM[nt][2] + dnw2 * ocP[nt][2];
            accO[nt][3] += den2 * ocM[nt][3] + dnw2 * ocP[nt][3];
        }
        cur ^= 1;
    }

    // ---- epilogue: + dense_b, vectorized float2 stores ----
    #pragma unroll
    for (int nt = 0; nt < 4; nt++) {
        int col0 = n0 + 8 * nt + 2 * tig;
        float2 db = *(const float2*)&dense_b[col0];
        size_t o1 = ((size_t)(b * Sn + s0 + m0 + g)) * 64 + col0;
        size_t o2 = ((size_t)(b * Sn + s0 + m0 + g + 8)) * 64 + col0;
        *(float2*)&out[o1] = make_float2(accO[nt][0] + db.x, accO[nt][1] + db.y);
        *(float2*)&out[o2] = make_float2(accO[nt][2] + db.x, accO[nt][3] + db.y);
    }
}

// ---------------------------------------------------------------------------
extern "C" void kernel_launch(void* const* d_in, const int* in_sizes, int n_in,
                              void* d_out, int out_size)
{
    const float4* query4  = (const float4*)d_in[0];
    const float4* key4    = (const float4*)d_in[1];
    const float4* value4  = (const float4*)d_in[2];
    // d_in[3] = attn_mask (unused by the math)
    const float2* wq_w2   = (const float2*)d_in[4];
    const float*  wq_b    = (const float*)d_in[5];
    const float4* wk_w4   = (const float4*)d_in[6];
    const float*  wk_b    = (const float*)d_in[7];
    const float*  wv_w    = (const float*)d_in[8];
    const float*  wv_b    = (const float*)d_in[9];
    const float*  dense_w = (const float*)d_in[10];
    const float*  dense_b = (const float*)d_in[11];
    float* out = (float*)d_out;

    constexpr int SM_KV  = (2304 * 3 + 4352 + 64 + 64 + 512) * 4;       // 47,360 B
    constexpr int SM_MP  = (128 * PAD + 3 * 64 * PAD + 128 + 64) * 4;   // 87,808 B
    constexpr int SM_OUT = W_END * 4;                                   // 76,544 B

    cudaFuncSetAttribute(kv_kernel,    cudaFuncAttributeMaxDynamicSharedMemorySize, SM_KV);
    cudaFuncSetAttribute(mprep_kernel, cudaFuncAttributeMaxDynamicSharedMemorySize, SM_MP);
    cudaFuncSetAttribute(out_kernel,   cudaFuncAttributeMaxDynamicSharedMemorySize, SM_OUT);

    wqprep_kernel<<<Hn, 256>>>(wq_w2);
    kv_kernel   <<<dim3(BHn, NSPLIT), 256, SM_KV >>>(key4, value4, wk_w4, wk_b);
    mprep_kernel<<<BHn,               256, SM_MP >>>(wv_w, wv_b, dense_w);
    out_kernel  <<<dim3(Sn / 64, Bn), 256, SM_OUT>>>(query4, wq_b, dense_b, out);
}

// round 17
// speedup vs baseline: 1.0318x; 1.0318x over previous
#include <cuda_runtime.h>
#include <cuda_fp16.h>

// ---------------- problem constants ----------------
constexpr int Bn = 4;
constexpr int Sn = 4096;
constexpr int Hn = 16;
constexpr int BHn = 64;
constexpr int NSPLIT = 16;
constexpr int SCHUNK = Sn / NSPLIT;   // 256
constexpr int CH  = 64;               // s-rows per staged chunk
constexpr int NCH = SCHUNK / CH;      // 4
constexpr float PIC = 3.1415f;        // verbatim constant from reference

// ---------------- static device scratch ----------------
__device__ float    g_part  [NSPLIT * 64 * 8192];  // slot x bh x [64x128] fp32 (KV | KVp)
__device__ float    g_partKs[NSPLIT * 64 * 128];   // slot x bh x [ksum|kpsum]
__device__ unsigned g_Mst   [64 * 4096];           // bh x {M halves [64x64] ; Mp halves}
__device__ float    g_Ks    [64 * 128];            // bh x stacked [Ksum;Kpsum] fp32
__device__ unsigned g_Wqh   [16 * 2048];           // h x Wq halves [d=64][n=64]

// ---------------- helpers ----------------
__device__ __forceinline__ void mma16h(float* c,
    unsigned a0, unsigned a1, unsigned a2, unsigned a3, unsigned b0, unsigned b1)
{
    asm volatile(
        "mma.sync.aligned.m16n8k16.row.col.f32.f16.f16.f32 "
        "{%0,%1,%2,%3},{%4,%5,%6,%7},{%8,%9},{%0,%1,%2,%3};"
        : "+f"(c[0]), "+f"(c[1]), "+f"(c[2]), "+f"(c[3])
        : "r"(a0), "r"(a1), "r"(a2), "r"(a3), "r"(b0), "r"(b1));
}
__device__ __forceinline__ void ldsm4t(unsigned& r0, unsigned& r1, unsigned& r2, unsigned& r3,
                                       unsigned addr)
{
    asm volatile("ldmatrix.sync.aligned.m8n8.x4.trans.shared.b16 {%0,%1,%2,%3}, [%4];"
        : "=r"(r0), "=r"(r1), "=r"(r2), "=r"(r3) : "r"(addr));
}
__device__ __forceinline__ unsigned h2u(float a, float b) {
    __half2 h = __floats2half2_rn(a, b);
    return *reinterpret_cast<unsigned*>(&h);
}
__device__ __forceinline__ void cpa16(unsigned dst, const void* src) {
    asm volatile("cp.async.cg.shared.global [%0], [%1], 16;" :: "r"(dst), "l"(src));
}
__device__ __forceinline__ void cpa_commit() { asm volatile("cp.async.commit_group;"); }
__device__ __forceinline__ void cpa_wait0()  { asm volatile("cp.async.wait_group 0;"); }
__device__ __forceinline__ float elu1(float v) { return v > 0.f ? v + 1.f : __expf(v); }

// ===========================================================================
// Kernel 0: convert Wq head slices to packed halves g_Wqh[h][d][n].
// ===========================================================================
__global__ __launch_bounds__(256)
void wqprep_kernel(const float2* __restrict__ wq_w2)
{
    const int h = blockIdx.x, tid = threadIdx.x;
    #pragma unroll
    for (int t = 0; t < 8; t++) {
        int w = tid + t * 256;            // word over 2048
        int d = w >> 5, cp = w & 31;
        float2 v = wq_w2[d * 512 + h * 32 + cp];
        g_Wqh[h * 2048 + w] = h2u(v.x, v.y);
    }
}

// ===========================================================================
// Kernel 1 (tensor, fp16 operands) — R14/R15-proven version (clock probe):
// ===========================================================================
__global__ __launch_bounds__(256, 2)
void kv_kernel(const float4* __restrict__ key4, const float4* __restrict__ value4,
               const float4* __restrict__ wk_w4, const float* __restrict__ wk_b)
{
    extern __shared__ unsigned smu[];
    unsigned* hWkw = smu;                 // Wk  [k=d][n] halves, stride 72h (36w): 2304w
    unsigned* hKw  = hWkw + 2304;         // rawK [s][d] halves, stride 72h: 2304w
    unsigned* hVw  = hKw  + 2304;         // [V|sinV] [s][z] halves, stride 136h (68w): 4352w
    unsigned* hAw  = hVw  + 4352;         // kp^T [x][s] halves, stride 72h: 2304w
    float* sSin  = (float*)(hAw + 2304);  // 64
    float* sBias = sSin + 64;             // 64
    float* sKred = sBias + 64;            // 4 x 128
    __half* hAh = (__half*)hAw;

    const int bh = blockIdx.x, split = blockIdx.y;
    const int b  = bh >> 4,   h     = bh & 15;
    const int tid = threadIdx.x;
    const int lane = tid & 31, wid = tid >> 5;
    const int g = lane >> 2, tig = lane & 3;
    const int sbase = split * SCHUNK;
    const int rowp = ((lane >> 3) & 1) * 8 + (lane & 7);
    const int colp = (lane >> 4) * 8;

    const unsigned wkBase = (unsigned)__cvta_generic_to_shared(hWkw);
    const unsigned vBase  = (unsigned)__cvta_generic_to_shared(hVw);

    #pragma unroll
    for (int t = 0; t < 4; t++) {
        int idx = tid + t * 256; int d = idx >> 4, c4 = idx & 15;
        float4 w = wk_w4[d * 256 + h * 16 + c4];
        *(uint2*)&hWkw[d * 36 + 2 * c4] = make_uint2(h2u(w.x, w.y), h2u(w.z, w.w));
    }
    if (tid < 64) sBias[tid] = wk_b[h * 64 + tid];

    #pragma unroll
    for (int t = 0; t < 4; t++) {
        int idx = tid + t * 256; int r = idx >> 4, c4 = idx & 15;
        size_t gi = ((size_t)(b * Sn + sbase + r)) * 16 + c4;
        float4 k = key4[gi], v = value4[gi];
        *(uint2*)&hKw[r * 36 + 2 * c4] = make_uint2(h2u(k.x, k.y), h2u(k.z, k.w));
        float sn = __sinf(PIC * (float)(sbase + r) / (float)Sn);
        *(uint2*)&hVw[r * 68 + 2 * c4]      = make_uint2(h2u(v.x, v.y), h2u(v.z, v.w));
        *(uint2*)&hVw[r * 68 + 32 + 2 * c4] = make_uint2(h2u(v.x*sn, v.y*sn), h2u(v.z*sn, v.w*sn));
    }
    if (tid < 64) sSin[tid] = __sinf(PIC * (float)(sbase + tid) / (float)Sn);
    __syncthreads();

    const int m0p = (wid & 3) * 16;
    const int n0p = (wid >> 2) * 32;
    const int x0 = (wid & 1) * 32;
    const int z0 = (wid >> 1) * 32;

    float acc[2][4][4];
    #pragma unroll
    for (int i = 0; i < 2; i++)
        #pragma unroll
        for (int nt = 0; nt < 4; nt++)
            #pragma unroll
            for (int j = 0; j < 4; j++) acc[i][nt][j] = 0.f;
    float kc[4][2], kpc[4][2];
    #pragma unroll
    for (int nt = 0; nt < 4; nt++) { kc[nt][0]=kc[nt][1]=kpc[nt][0]=kpc[nt][1]=0.f; }

    for (int cc = 0; cc < NCH; cc++) {
        float pc[4][4];
        #pragma unroll
        for (int nt = 0; nt < 4; nt++) {
            int col0 = n0p + 8 * nt + 2 * tig;
            pc[nt][0] = sBias[col0]; pc[nt][1] = sBias[col0 + 1];
            pc[nt][2] = sBias[col0]; pc[nt][3] = sBias[col0 + 1];
        }
        #pragma unroll
        for (int ks = 0; ks < 4; ks++) {
            int kw = ks * 8;
            unsigned a0 = hKw[(m0p + g)     * 36 + kw + tig];
            unsigned a1 = hKw[(m0p + g + 8) * 36 + kw + tig];
            unsigned a2 = hKw[(m0p + g)     * 36 + kw + tig + 4];
            unsigned a3 = hKw[(m0p + g + 8) * 36 + kw + tig + 4];
            #pragma unroll
            for (int p = 0; p < 2; p++) {
                unsigned b0, b1, b2, b3;
                unsigned ad = wkBase + ((16 * ks + rowp) * 72 + n0p + 16 * p + colp) * 2;
                ldsm4t(b0, b1, b2, b3, ad);
                mma16h(pc[2 * p],     a0, a1, a2, a3, b0, b1);
                mma16h(pc[2 * p + 1], a0, a1, a2, a3, b2, b3);
            }
        }

        {
            int s1 = m0p + g, s2 = m0p + g + 8;
            float sn1 = sSin[s1], sn2 = sSin[s2];
            #pragma unroll
            for (int nt = 0; nt < 4; nt++) {
                int col0 = n0p + 8 * nt + 2 * tig;
                float v00 = elu1(pc[nt][0]), v01 = elu1(pc[nt][1]);
                float v10 = elu1(pc[nt][2]), v11 = elu1(pc[nt][3]);
                kc [nt][0] += v00 + v10;           kc [nt][1] += v01 + v11;
                kpc[nt][0] += v00*sn1 + v10*sn2;   kpc[nt][1] += v01*sn1 + v11*sn2;
                hAh[(col0)     * 72 + s1] = __float2half_rn(v00);
                hAh[(col0 + 1) * 72 + s1] = __float2half_rn(v01);
                hAh[(col0)     * 72 + s2] = __float2half_rn(v10);
                hAh[(col0 + 1) * 72 + s2] = __float2half_rn(v11);
            }
        }
        __syncthreads();

        #pragma unroll
        for (int ks = 0; ks < 4; ks++) {
            int kw = ks * 8;
            unsigned a[2][4];
            #pragma unroll
            for (int i = 0; i < 2; i++) {
                int xr = x0 + 16 * i + g;
                a[i][0] = hAw[xr       * 36 + kw + tig];
                a[i][1] = hAw[(xr + 8) * 36 + kw + tig];
                a[i][2] = hAw[xr       * 36 + kw + tig + 4];
                a[i][3] = hAw[(xr + 8) * 36 + kw + tig + 4];
            }
            #pragma unroll
            for (int p = 0; p < 2; p++) {
                unsigned b0, b1, b2, b3;
                unsigned ad = vBase + ((16 * ks + rowp) * 136 + z0 + 16 * p + colp) * 2;
                ldsm4t(b0, b1, b2, b3, ad);
                #pragma unroll
                for (int i = 0; i < 2; i++) {
                    mma16h(acc[i][2 * p],     a[i][0], a[i][1], a[i][2], a[i][3], b0, b1);
                    mma16h(acc[i][2 * p + 1], a[i][0], a[i][1], a[i][2], a[i][3], b2, b3);
                }
            }
        }
        __syncthreads();

        if (cc + 1 < NCH) {
            int scs = sbase + (cc + 1) * CH;
            #pragma unroll
            for (int t = 0; t < 4; t++) {
                int idx = tid + t * 256; int r = idx >> 4, c4 = idx & 15;
                size_t gi = ((size_t)(b * Sn + scs + r)) * 16 + c4;
                float4 k = key4[gi], v = value4[gi];
                *(uint2*)&hKw[r * 36 + 2 * c4] = make_uint2(h2u(k.x, k.y), h2u(k.z, k.w));
                float sn = __sinf(PIC * (float)(scs + r) / (float)Sn);
                *(uint2*)&hVw[r * 68 + 2 * c4]      = make_uint2(h2u(v.x, v.y), h2u(v.z, v.w));
                *(uint2*)&hVw[r * 68 + 32 + 2 * c4] = make_uint2(h2u(v.x*sn, v.y*sn), h2u(v.z*sn, v.w*sn));
            }
            if (tid < 64) sSin[tid] = __sinf(PIC * (float)(scs + tid) / (float)Sn);
            __syncthreads();
        }
    }

    {
        size_t base = ((size_t)(split * 64 + bh)) * 8192;
        #pragma unroll
        for (int i = 0; i < 2; i++)
            #pragma unroll
            for (int nt = 0; nt < 4; nt++) {
                int x = x0 + 16 * i + g;
                int z = z0 + 8 * nt + 2 * tig;
                *(float2*)&g_part[base + (size_t)x       * 128 + z] = make_float2(acc[i][nt][0], acc[i][nt][1]);
                *(float2*)&g_part[base + (size_t)(x + 8) * 128 + z] = make_float2(acc[i][nt][2], acc[i][nt][3]);
            }
    }

    #pragma unroll
    for (int off = 4; off <= 16; off <<= 1)
        #pragma unroll
        for (int nt = 0; nt < 4; nt++)
            #pragma unroll
            for (int e = 0; e < 2; e++) {
                kc [nt][e] += __shfl_xor_sync(0xffffffffu, kc [nt][e], off);
                kpc[nt][e] += __shfl_xor_sync(0xffffffffu, kpc[nt][e], off);
            }
    if (g == 0) {
        int mt = wid & 3;
        #pragma unroll
        for (int nt = 0; nt < 4; nt++)
            #pragma unroll
            for (int e = 0; e < 2; e++) {
                int x = n0p + 8 * nt + 2 * tig + e;
                sKred[mt * 128 + x]      = kc [nt][e];
                sKred[mt * 128 + 64 + x] = kpc[nt][e];
            }
    }
    __syncthreads();
    if (tid < 128)
        g_partKs[(split * 64 + bh) * 128 + tid] =
            sKred[tid] + sKred[128 + tid] + sKred[256 + tid] + sKred[384 + tid];
}

// ===========================================================================
// Kernel 2: per bh — reduce partials, fold V-proj + dense (R15):
//   M/Mp -> g_Mst as PACKED HALF matrices [bh][{M,Mp}][k=64][n=64].
// ===========================================================================
constexpr int PAD = 68;
__global__ __launch_bounds__(256)
void mprep_kernel(const float* __restrict__ wv_w, const float* __restrict__ wv_b,
                  const float* __restrict__ dense_w)
{
    extern __shared__ float sm[];
    float* sC    = sm;                   // 128*68
    float* sWv   = sC   + 128 * PAD;
    float* sWd   = sWv  + 64 * PAD;
    float* sG    = sWd  + 64 * PAD;
    float* sKsum = sG   + 64 * PAD;      // 128
    float* sBvd  = sKsum + 128;          // 64
    const float4* g_part4 = (const float4*)g_part;

    const int bh = blockIdx.x, h = bh & 15, tid = threadIdx.x;

    #pragma unroll
    for (int t = 0; t < 16; t++) {
        int i = tid + t * 256; int k = i >> 6, c = i & 63;
        sWv[k * PAD + c] = wv_w[k * 1024 + h * 64 + c];
        sWd[k * PAD + c] = dense_w[(h * 64 + k) * 64 + c];
    }
    #pragma unroll
    for (int t = 0; t < 8; t++) {
        int idx = tid + t * 256;
        int x = idx >> 5, c8 = idx & 31;
        float4 s = make_float4(0.f, 0.f, 0.f, 0.f);
        for (int sl = 0; sl < NSPLIT; sl++) {
            float4 v = g_part4[((size_t)(sl * 64 + bh)) * 2048 + idx];
            s.x += v.x; s.y += v.y; s.z += v.z; s.w += v.w;
        }
        int row = (c8 < 16) ? x : (x + 64);
        int c4  = c8 & 15;
        *(float4*)&sC[row * PAD + c4 * 4] = s;
    }
    if (tid < 128) {
        float s = 0.f;
        for (int sl = 0; sl < NSPLIT; sl++) s += g_partKs[(sl * 64 + bh) * 128 + tid];
        sKsum[tid] = s;
        g_Ks[bh * 128 + tid] = s;
    }
    __syncthreads();

    const int r  = tid >> 2;
    const int c0 = (tid & 3) * 16;

    {
        float a16[16];
        #pragma unroll
        for (int j = 0; j < 16; j++) a16[j] = 0.f;
        for (int kk = 0; kk < 64; kk++) {
            float a = sWv[r * PAD + kk];
            #pragma unroll
            for (int j = 0; j < 16; j++) a16[j] += a * sWd[kk * PAD + c0 + j];
        }
        #pragma unroll
        for (int j = 0; j < 16; j++) sG[r * PAD + c0 + j] = a16[j];
    }
    if (tid < 64) {
        float s = 0.f;
        for (int c = 0; c < 64; c++) s += wv_b[h * 64 + c] * sWd[c * PAD + tid];
        sBvd[tid] = s;
    }
    __syncthreads();

    {
        float m0[16], m1[16];
        #pragma unroll
        for (int j = 0; j < 16; j++) { m0[j] = 0.f; m1[j] = 0.f; }
        for (int kk = 0; kk < 64; kk++) {
            float a0 = sC[r * PAD + kk];
            float a1 = sC[(r + 64) * PAD + kk];
            #pragma unroll
            for (int j = 0; j < 16; j++) {
                float gv = sG[kk * PAD + c0 + j];
                m0[j] += a0 * gv; m1[j] += a1 * gv;
            }
        }
        float k0 = sKsum[r], k1 = sKsum[r + 64];
        #pragma unroll
        for (int j = 0; j < 16; j++) {
            m0[j] += k0 * sBvd[c0 + j];
            m1[j] += k1 * sBvd[c0 + j];
        }
        unsigned* dstW = &g_Mst[(size_t)bh * 4096];
        #pragma unroll
        for (int j = 0; j < 16; j += 2) {
            dstW[r * 32 + (c0 + j) / 2]        = h2u(m0[j], m0[j + 1]);
            dstW[2048 + r * 32 + (c0 + j) / 2] = h2u(m1[j], m1[j + 1]);
        }
    }
}

// ===========================================================================
// Kernel 3 (tensor, fp16, cp.async double-buffered staging):
//   per (b, 64-row s-tile), loop heads; all per-head operands (Wq halves,
//   M/Mp halves, Ks, bq) arrive via cp.async overlapped with prior head.
// ===========================================================================
constexpr int W_QRAW = 0;
constexpr int W_Q    = 2304;
constexpr int W_BUF  = 4608;
constexpr int BUFW   = 7104;   // hWq 2304 | hM 2304 | hMp 2304 | Ks 128 | Qb 64
constexpr int W_WS   = W_BUF + 2 * BUFW;   // 18816
constexpr int W_DOT  = W_WS + 64;          // 18880
constexpr int W_END  = W_DOT + 256;        // 19136 words = 76544 B

__global__ __launch_bounds__(256, 2)
void out_kernel(const float4* __restrict__ query4,
                const float*  __restrict__ wq_b,
                const float*  __restrict__ dense_b, float* __restrict__ out)
{
    extern __shared__ unsigned smu[];
    unsigned* hQraw = smu + W_QRAW;
    unsigned* hQ    = smu + W_Q;
    float* sWs  = (float*)(smu + W_WS);
    float* sDot = (float*)(smu + W_DOT);
    __half* hQh = (__half*)hQ;

    const int b  = blockIdx.y;
    const int s0 = blockIdx.x * 64;
    const int tid = threadIdx.x;
    const int lane = tid & 31, wid = tid >> 5;
    const int g = lane >> 2, tig = lane & 3;
    const int mt = wid & 3, nh = wid >> 2;
    const int m0 = mt * 16, n0 = nh * 32;
    const int rowp = ((lane >> 3) & 1) * 8 + (lane & 7);
    const int colp = (lane >> 4) * 8;

    const unsigned smemBase = (unsigned)__cvta_generic_to_shared(smu);

    // issue cp.async staging for head hh into buffer `buf`
    auto stage = [&](int buf, int hh) {
        unsigned base = smemBase + (W_BUF + buf * BUFW) * 4;
        #pragma unroll
        for (int t = 0; t < 2; t++) {                       // Wq: 512 x 16B
            int idx = tid + t * 256; int d = idx >> 3, cc = idx & 7;
            cpa16(base + d * 144 + cc * 16,
                  (const char*)g_Wqh + (size_t)hh * 8192 + d * 128 + cc * 16);
        }
        #pragma unroll
        for (int t = 0; t < 4; t++) {                       // M/Mp: 1024 x 16B
            int idx = tid + t * 256; int mat = idx >> 9, r = (idx >> 3) & 63, cc = idx & 7;
            cpa16(base + (2304 + mat * 2304) * 4 + r * 144 + cc * 16,
                  (const char*)g_Mst + (size_t)(b * 16 + hh) * 16384 + mat * 8192 + r * 128 + cc * 16);
        }
        if (tid < 32)                                       // Ks: 512B
            cpa16(base + 6912 * 4 + tid * 16,
                  (const char*)g_Ks + (size_t)(b * 16 + hh) * 512 + tid * 16);
        else if (tid < 48)                                  // Qb: 256B
            cpa16(base + 7040 * 4 + (tid - 32) * 16,
                  (const char*)wq_b + (size_t)hh * 256 + (tid - 32) * 16);
        cpa_commit();
    };

    // prologue: start head 0 copies, then stage raw Q halves + pos weights
    stage(0, 0);
    #pragma unroll
    for (int t = 0; t < 4; t++) {
        int idx = tid + t * 256; int r = idx >> 4, c4 = idx & 15;
        float4 q = query4[((size_t)(b * Sn + s0 + r)) * 16 + c4];
        *(uint2*)&hQraw[r * 36 + 2 * c4] = make_uint2(h2u(q.x, q.y), h2u(q.z, q.w));
    }
    if (tid < 64) {
        float ps = PIC * (float)(s0 + tid) / (float)Sn;
        sWs[tid] = __cosf(ps) + __sinf(ps);
    }

    float accO[4][4];
    #pragma unroll
    for (int nt = 0; nt < 4; nt++)
        #pragma unroll
        for (int j = 0; j < 4; j++) accO[nt][j] = 0.f;

    int cur = 0;
    for (int h = 0; h < Hn; h++) {
        cpa_wait0();
        __syncthreads();                 // buf[cur] ready for all; prev readers done
        if (h + 1 < Hn) stage(cur ^ 1, h + 1);

        unsigned* hQ2 = hQ;
        unsigned* hWq = smu + W_BUF + cur * BUFW;
        float* sKs = (float*)(hWq + 6912);
        float* sQb = (float*)(hWq + 7040);
        const unsigned wqBase = smemBase + (W_BUF + cur * BUFW) * 4;
        const unsigned mBase  = wqBase + 2304 * 4;
        const unsigned mpBase = wqBase + 4608 * 4;

        // ---- q projection mma (f16 k16) ----
        float pc[4][4];
        #pragma unroll
        for (int nt = 0; nt < 4; nt++) {
            int col0 = n0 + 8 * nt + 2 * tig;
            pc[nt][0] = sQb[col0]; pc[nt][1] = sQb[col0 + 1];
            pc[nt][2] = sQb[col0]; pc[nt][3] = sQb[col0 + 1];
        }
        #pragma unroll
        for (int ks = 0; ks < 4; ks++) {
            int kw = ks * 8;
            unsigned a0 = hQraw[(m0 + g)     * 36 + kw + tig];
            unsigned a1 = hQraw[(m0 + g + 8) * 36 + kw + tig];
            unsigned a2 = hQraw[(m0 + g)     * 36 + kw + tig + 4];
            unsigned a3 = hQraw[(m0 + g + 8) * 36 + kw + tig + 4];
            #pragma unroll
            for (int p = 0; p < 2; p++) {
                unsigned b0, b1, b2, b3;
                unsigned ad = wqBase + ((16 * ks + rowp) * 72 + n0 + 16 * p + colp) * 2;
                ldsm4t(b0, b1, b2, b3, ad);
                mma16h(pc[2 * p],     a0, a1, a2, a3, b0, b1);
                mma16h(pc[2 * p + 1], a0, a1, a2, a3, b2, b3);
            }
        }

        // ---- elu, partial denominators, half-store q [s][x] ----
        {
            int r1 = (m0 + g) * 72, r2 = (m0 + g + 8) * 72;
            float d0a = 0.f, d1a = 0.f, d0b = 0.f, d1b = 0.f;
            #pragma unroll
            for (int nt = 0; nt < 4; nt++) {
                int col0 = n0 + 8 * nt + 2 * tig;
                float ks0 = sKs[col0],      ks1 = sKs[col0 + 1];
                float kp0 = sKs[64 + col0], kp1 = sKs[64 + col0 + 1];
                float v00 = elu1(pc[nt][0]), v01 = elu1(pc[nt][1]);
                float v10 = elu1(pc[nt][2]), v11 = elu1(pc[nt][3]);
                d0a += v00 * ks0 + v01 * ks1;  d1a += v00 * kp0 + v01 * kp1;
                d0b += v10 * ks0 + v11 * ks1;  d1b += v10 * kp0 + v11 * kp1;
                hQh[r1 + col0]     = __float2half_rn(v00);
                hQh[r1 + col0 + 1] = __float2half_rn(v01);
                hQh[r2 + col0]     = __float2half_rn(v10);
                hQh[r2 + col0 + 1] = __float2half_rn(v11);
            }
            d0a += __shfl_xor_sync(0xffffffffu, d0a, 1); d0a += __shfl_xor_sync(0xffffffffu, d0a, 2);
            d1a += __shfl_xor_sync(0xffffffffu, d1a, 1); d1a += __shfl_xor_sync(0xffffffffu, d1a, 2);
            d0b += __shfl_xor_sync(0xffffffffu, d0b, 1); d0b += __shfl_xor_sync(0xffffffffu, d0b, 2);
            d1b += __shfl_xor_sync(0xffffffffu, d1b, 1); d1b += __shfl_xor_sync(0xffffffffu, d1b, 2);
            if (tig == 0) {
                sDot[(m0 + g) * 4 + nh]         = d0a;
                sDot[(m0 + g) * 4 + 2 + nh]     = d1a;
                sDot[(m0 + g + 8) * 4 + nh]     = d0b;
                sDot[(m0 + g + 8) * 4 + 2 + nh] = d1b;
            }
        }
        __syncthreads();

        int r1 = m0 + g, r2 = m0 + g + 8;
        float w1 = sWs[r1], w2 = sWs[r2];
        float den1 = 1.0f / (sDot[r1 * 4] + sDot[r1 * 4 + 1]
                     + w1 * (sDot[r1 * 4 + 2] + sDot[r1 * 4 + 3]) + 1e-5f);
        float den2 = 1.0f / (sDot[r2 * 4] + sDot[r2 * 4 + 1]
                     + w2 * (sDot[r2 * 4 + 2] + sDot[r2 * 4 + 3]) + 1e-5f);
        float dnw1 = den1 * w1, dnw2 = den2 * w2;

        // ---- split o-GEMM (f16 k16) ----
        float ocM[4][4], ocP[4][4];
        #pragma unroll
        for (int nt = 0; nt < 4; nt++)
            #pragma unroll
            for (int j = 0; j < 4; j++) { ocM[nt][j] = 0.f; ocP[nt][j] = 0.f; }
        #pragma unroll
        for (int ks = 0; ks < 4; ks++) {
            int kw = ks * 8;
            unsigned a0 = hQ2[(m0 + g)     * 36 + kw + tig];
            unsigned a1 = hQ2[(m0 + g + 8) * 36 + kw + tig];
            unsigned a2 = hQ2[(m0 + g)     * 36 + kw + tig + 4];
            unsigned a3 = hQ2[(m0 + g + 8) * 36 + kw + tig + 4];
            #pragma unroll
            for (int p = 0; p < 2; p++) {
                unsigned rowoff = ((16 * ks + rowp) * 72 + n0 + 16 * p + colp) * 2;
                unsigned b0, b1, b2, b3;
                ldsm4t(b0, b1, b2, b3, mBase + rowoff);
                mma16h(ocM[2 * p],     a0, a1, a2, a3, b0, b1);
                mma16h(ocM[2 * p + 1], a0, a1, a2, a3, b2, b3);
                ldsm4t(b0, b1, b2, b3, mpBase + rowoff);
                mma16h(ocP[2 * p],     a0, a1, a2, a3, b0, b1);
                mma16h(ocP[2 * p + 1], a0, a1, a2, a3, b2, b3);
            }
        }
        #pragma unroll
        for (int nt = 0; nt < 4; nt++) {
            accO[nt][0] += den1 * ocM[nt][0] + dnw1 * ocP[nt][0];
            accO[nt][1] += den1 * ocM[nt][1] + dnw1 * ocP[nt][1];
            accO[nt][2] += den2 * ocM[nt][2] + dnw2 * ocP[nt][2];
            accO[nt][3] += den2 * ocM[nt][3] + dnw2 * ocP[nt][3];
        }
        cur ^= 1;
    }

    // ---- epilogue: + dense_b, vectorized float2 stores ----
    #pragma unroll
    for (int nt = 0; nt < 4; nt++) {
        int col0 = n0 + 8 * nt + 2 * tig;
        float2 db = *(const float2*)&dense_b[col0];
        size_t o1 = ((size_t)(b * Sn + s0 + m0 + g)) * 64 + col0;
        size_t o2 = ((size_t)(b * Sn + s0 + m0 + g + 8)) * 64 + col0;
        *(float2*)&out[o1] = make_float2(accO[nt][0] + db.x, accO[nt][1] + db.y);
        *(float2*)&out[o2] = make_float2(accO[nt][2] + db.x, accO[nt][3] + db.y);
    }
}

// ---------------------------------------------------------------------------
extern "C" void kernel_launch(void* const* d_in, const int* in_sizes, int n_in,
                              void* d_out, int out_size)
{
    const float4* query4  = (const float4*)d_in[0];
    const float4* key4    = (const float4*)d_in[1];
    const float4* value4  = (const float4*)d_in[2];
    // d_in[3] = attn_mask (unused by the math)
    const float2* wq_w2   = (const float2*)d_in[4];
    const float*  wq_b    = (const float*)d_in[5];
    const float4* wk_w4   = (const float4*)d_in[6];
    const float*  wk_b    = (const float*)d_in[7];
    const float*  wv_w    = (const float*)d_in[8];
    const float*  wv_b    = (const float*)d_in[9];
    const float*  dense_w = (const float*)d_in[10];
    const float*  dense_b = (const float*)d_in[11];
    float* out = (float*)d_out;

    constexpr int SM_KV  = (2304 * 3 + 4352 + 64 + 64 + 512) * 4;       // 47,360 B
    constexpr int SM_MP  = (128 * PAD + 3 * 64 * PAD + 128 + 64) * 4;   // 87,808 B
    constexpr int SM_OUT = W_END * 4;                                   // 76,544 B

    cudaFuncSetAttribute(kv_kernel,    cudaFuncAttributeMaxDynamicSharedMemorySize, SM_KV);
    cudaFuncSetAttribute(mprep_kernel, cudaFuncAttributeMaxDynamicSharedMemorySize, SM_MP);
    cudaFuncSetAttribute(out_kernel,   cudaFuncAttributeMaxDynamicSharedMemorySize, SM_OUT);

    wqprep_kernel<<<Hn, 256>>>(wq_w2);
    kv_kernel   <<<dim3(BHn, NSPLIT), 256, SM_KV >>>(key4, value4, wk_w4, wk_b);
    mprep_kernel<<<BHn,               256, SM_MP >>>(wv_w, wv_b, dense_w);
    out_kernel  <<<dim3(Sn / 64, Bn), 256, SM_OUT>>>(query4, wq_b, dense_b, out);
}